// round 13
// baseline (speedup 1.0000x reference)
#include <cuda_runtime.h>
#include <cuda_fp16.h>
#include <cstdint>

#define N_NODES  50000
#define N_EDGES  800000
#define N_GRAPHS 128
#define D        128
#define SCAN_BLKS ((N_NODES + 1023) / 1024)   // 49
#define NA 25088                              // half A (196 gemm tiles)

// ---------------- scratch (device globals; no allocation allowed) ----------
__device__ __half g_xb[N_NODES * D];   // x fp16; later reused as gemm2 output
__device__ __half g_hw[N_NODES * D];   // gemm1 / gemm3 output (scaled by dinv)
__device__ __half g_hb[N_NODES * D];   // aggregation output (activations)
__device__ __half g_wt[3 * D * D];     // transposed weights [N][K] fp16
__device__ int    g_degi[N_NODES];
__device__ float  g_dinv[N_NODES];
__device__ int    g_scan[N_NODES];
__device__ int    g_bsum[SCAN_BLKS];
__device__ int    g_boff[SCAN_BLKS];
__device__ int    g_rowptr[N_NODES + 1];
__device__ int    g_cursor[N_NODES];
__device__ int    g_csr[N_EDGES];
__device__ float  g_gs[N_GRAPHS * D];
__device__ float  g_gcnt[N_GRAPHS];

// ---------------- small helpers --------------------------------------------
__device__ __forceinline__ unsigned hpack(float lo, float hi) {
    unsigned r;
    asm("cvt.rn.f16x2.f32 %0, %1, %2;" : "=r"(r) : "f"(hi), "f"(lo));
    return r;
}
__device__ __forceinline__ float4 h2f4(uint2 p) {
    __half2 a = *reinterpret_cast<__half2*>(&p.x);
    __half2 b = *reinterpret_cast<__half2*>(&p.y);
    float2 fa = __half22float2(a);
    float2 fb = __half22float2(b);
    return make_float4(fa.x, fa.y, fb.x, fb.y);
}
__device__ __forceinline__ void acc4(float4& a, float4 t) {
    a.x += t.x; a.y += t.y; a.z += t.z; a.w += t.w;
}
__device__ __forceinline__ uint32_t smem_u32(const void* p) {
    uint32_t a;
    asm("{ .reg .u64 t; cvta.to.shared.u64 t, %1; cvt.u32.u64 %0, t; }"
        : "=r"(a) : "l"(p));
    return a;
}

// ---------------- mma helpers ------------------------------------------------
__device__ __forceinline__ void ldsm_x4(uint32_t& r0, uint32_t& r1,
                                        uint32_t& r2, uint32_t& r3,
                                        uint32_t addr) {
    asm volatile("ldmatrix.sync.aligned.m8n8.x4.shared.b16 {%0,%1,%2,%3}, [%4];"
                 : "=r"(r0), "=r"(r1), "=r"(r2), "=r"(r3) : "r"(addr));
}
__device__ __forceinline__ void ldsm_x2(uint32_t& r0, uint32_t& r1,
                                        uint32_t addr) {
    asm volatile("ldmatrix.sync.aligned.m8n8.x2.shared.b16 {%0,%1}, [%2];"
                 : "=r"(r0), "=r"(r1) : "r"(addr));
}
__device__ __forceinline__ void mma16816(float& d0, float& d1, float& d2, float& d3,
                                         uint32_t a0, uint32_t a1, uint32_t a2,
                                         uint32_t a3, uint32_t b0, uint32_t b1) {
    asm volatile(
        "mma.sync.aligned.m16n8k16.row.col.f32.f16.f16.f32 "
        "{%0,%1,%2,%3}, {%4,%5,%6,%7}, {%8,%9}, {%0,%1,%2,%3};"
        : "+f"(d0), "+f"(d1), "+f"(d2), "+f"(d3)
        : "r"(a0), "r"(a1), "r"(a2), "r"(a3), "r"(b0), "r"(b1));
}

// ---------------- setup kernels (R8-exact) ----------------------------------
__global__ void zero_kernel() {
    int i = blockIdx.x * blockDim.x + threadIdx.x;
    if (i < N_NODES) g_degi[i] = 0;
    if (i < N_GRAPHS * D) g_gs[i] = 0.f;
    if (i < N_GRAPHS) g_gcnt[i] = 0.f;
}

__global__ void hist_count_kernel(const int* __restrict__ col,
                                  const int* __restrict__ batch) {
    int i = blockIdx.x * blockDim.x + threadIdx.x;
    if (i < N_EDGES) atomicAdd(&g_degi[col[i]], 1);
    if (i < N_NODES) atomicAdd(&g_gcnt[batch[i]], 1.0f);
}

__global__ void scan_part_kernel() {
    __shared__ int wsum[32];
    int tid = threadIdx.x, lane = tid & 31, wid = tid >> 5;
    int idx = blockIdx.x * 1024 + tid;
    int v = (idx < N_NODES) ? g_degi[idx] : 0;
    if (idx < N_NODES) g_dinv[idx] = rsqrtf((float)(v + 1));
    int x = v;
    #pragma unroll
    for (int s = 1; s < 32; s <<= 1) {
        int t = __shfl_up_sync(0xffffffffu, x, s);
        if (lane >= s) x += t;
    }
    if (lane == 31) wsum[wid] = x;
    __syncthreads();
    if (wid == 0) {
        int y = wsum[lane];
        #pragma unroll
        for (int s = 1; s < 32; s <<= 1) {
            int t = __shfl_up_sync(0xffffffffu, y, s);
            if (lane >= s) y += t;
        }
        wsum[lane] = y;
    }
    __syncthreads();
    int incl = x + (wid ? wsum[wid - 1] : 0);
    if (idx < N_NODES) g_scan[idx] = incl;
    if (tid == 1023) g_bsum[blockIdx.x] = incl;
}

__global__ void scan_bsum_kernel() {
    int lane = threadIdx.x;
    int x0 = (lane < SCAN_BLKS) ? g_bsum[lane] : 0;
    int x1 = (lane + 32 < SCAN_BLKS) ? g_bsum[lane + 32] : 0;
    int i0 = x0;
    #pragma unroll
    for (int s = 1; s < 32; s <<= 1) {
        int t = __shfl_up_sync(0xffffffffu, i0, s);
        if (lane >= s) i0 += t;
    }
    int tot0 = __shfl_sync(0xffffffffu, i0, 31);
    int i1 = x1;
    #pragma unroll
    for (int s = 1; s < 32; s <<= 1) {
        int t = __shfl_up_sync(0xffffffffu, i1, s);
        if (lane >= s) i1 += t;
    }
    if (lane < SCAN_BLKS) g_boff[lane] = i0 - x0;
    if (lane + 32 < SCAN_BLKS) g_boff[lane + 32] = tot0 + i1 - x1;
}

__global__ void scan_final_kernel() {
    int idx = blockIdx.x * blockDim.x + threadIdx.x;
    if (idx == 0) g_rowptr[0] = 0;
    if (idx < N_NODES) {
        int incl = g_scan[idx] + g_boff[idx >> 10];
        g_rowptr[idx + 1] = incl;
        g_cursor[idx]     = incl - g_degi[idx];
    }
}

__global__ void scatter_kernel(const int* __restrict__ row,
                               const int* __restrict__ col) {
    int e = blockIdx.x * blockDim.x + threadIdx.x;
    if (e < N_EDGES) {
        int c = col[e];
        int p = atomicAdd(&g_cursor[c], 1);
        g_csr[p] = row[e];
    }
}

__global__ void conv_kernel(const float* __restrict__ x,
                            const float* __restrict__ W1,
                            const float* __restrict__ W2,
                            const float* __restrict__ W3) {
    int i = blockIdx.x * blockDim.x + threadIdx.x;
    if (i < N_NODES * (D / 4)) {
        float4 v = ((const float4*)x)[i];
        uint2 o;
        o.x = hpack(v.x, v.y);
        o.y = hpack(v.z, v.w);
        ((uint2*)g_xb)[i] = o;
    }
    if (i < 3 * D * D) {
        int l = i >> 14;
        int r = i & (D * D - 1);
        int k = r >> 7, n = r & 127;
        const float* W = (l == 0) ? W1 : ((l == 1) ? W2 : W3);
        g_wt[l * D * D + n * D + k] = __float2half(W[k * D + n]);
    }
}

// ---------------- shared GEMM pieces ----------------------------------------
#define SM_STRIDE 136
#define SM_ROWB   (SM_STRIDE * 2)
#define SM_A_OFF  0
#define SM_B_OFF  (128 * SM_ROWB)
#define SM_TOT    (2 * 128 * SM_ROWB)

__device__ __forceinline__ void stage_B(char* smem, const __half* Wt, int tid) {
    const uint4* Bin = (const uint4*)Wt;
    #pragma unroll 4
    for (int i = tid; i < 2048; i += 256) {
        int r = i >> 4, g = i & 15;
        *(uint4*)(smem + SM_B_OFF + r * SM_ROWB + g * 16) = Bin[i];
    }
}

__device__ __forceinline__ void mma_body(char* smem, uint32_t sb,
                                         __half* __restrict__ out,
                                         int row0, int n, int wid, int lane) {
    int m_base = wid * 16;
    uint32_t a_addr = sb + SM_A_OFF
                    + (uint32_t)(m_base + (lane & 15)) * SM_ROWB
                    + (uint32_t)(lane >> 4) * 16;
    uint32_t b_addr = sb + SM_B_OFF
                    + (uint32_t)(lane & 7) * SM_ROWB
                    + (uint32_t)((lane >> 3) & 1) * 16;

    float acc[16][4];
    #pragma unroll
    for (int j = 0; j < 16; j++)
        #pragma unroll
        for (int q = 0; q < 4; q++) acc[j][q] = 0.f;

    #pragma unroll
    for (int kk = 0; kk < 8; kk++) {
        uint32_t a0, a1, a2, a3;
        ldsm_x4(a0, a1, a2, a3, a_addr + kk * 32);
        #pragma unroll
        for (int j = 0; j < 16; j++) {
            uint32_t b0, b1;
            ldsm_x2(b0, b1, b_addr + (uint32_t)j * 8 * SM_ROWB + kk * 32);
            mma16816(acc[j][0], acc[j][1], acc[j][2], acc[j][3],
                     a0, a1, a2, a3, b0, b1);
        }
    }

    int quad = lane >> 2;
    int tcol = (lane & 3) * 2;
    int r0 = row0 + m_base + quad;
    int r1 = r0 + 8;
    float dv0 = (r0 < n) ? g_dinv[r0] : 0.f;
    float dv1 = (r1 < n) ? g_dinv[r1] : 0.f;
    unsigned* o0 = (unsigned*)(out + (size_t)(r0 < n ? r0 : 0) * D);
    unsigned* o1 = (unsigned*)(out + (size_t)(r1 < n ? r1 : 0) * D);
    #pragma unroll
    for (int j = 0; j < 16; j++) {
        int nc = j * 8 + tcol;
        if (r0 < n) o0[nc >> 1] = hpack(acc[j][0] * dv0, acc[j][1] * dv0);
        if (r1 < n) o1[nc >> 1] = hpack(acc[j][2] * dv1, acc[j][3] * dv1);
    }
}

// GEMM over rows [rbase, rbase + 128*gridDim), bounded by n
__global__ void __launch_bounds__(256, 2)
mma_gemm_kernel(const __half* __restrict__ in,
                const __half* __restrict__ Wt,
                __half* __restrict__ out, int rbase, int n) {
    extern __shared__ char smem[];
    uint32_t sb = smem_u32(smem);
    int tid = threadIdx.x, wid = tid >> 5, lane = tid & 31;
    int row0 = rbase + blockIdx.x * 128;

    const uint4* Ain = (const uint4*)(in + (size_t)row0 * D);
    #pragma unroll 4
    for (int i = tid; i < 2048; i += 256) {
        int r = i >> 4, g = i & 15;
        uint4 va = make_uint4(0u, 0u, 0u, 0u);
        if (row0 + r < n) va = Ain[i];
        *(uint4*)(smem + SM_A_OFF + r * SM_ROWB + g * 16) = va;
    }
    stage_B(smem, Wt, tid);
    __syncthreads();
    mma_body(smem, sb, out, row0, n, wid, lane);
}

// ---------------- aggregation: warp per node, fp16 gather, fp32 acc --------
// processes nodes [vbase, vend)
__global__ void agg_kernel(const uint2* __restrict__ hw,
                           const float* __restrict__ bias,
                           uint2* __restrict__ out, int relu,
                           int vbase, int vend) {
    int gt = blockIdx.x * blockDim.x + threadIdx.x;
    int v = vbase + (gt >> 5);
    int lane = gt & 31;
    if (v >= vend) return;

    float4 acc = h2f4(hw[v * 32 + lane]);
    int s = g_rowptr[v], e = g_rowptr[v + 1];
    int i = s;
    for (; i + 8 <= e; i += 8) {
        int u0 = g_csr[i],     u1 = g_csr[i + 1];
        int u2 = g_csr[i + 2], u3 = g_csr[i + 3];
        int u4 = g_csr[i + 4], u5 = g_csr[i + 5];
        int u6 = g_csr[i + 6], u7 = g_csr[i + 7];
        uint2 p0 = hw[u0 * 32 + lane];
        uint2 p1 = hw[u1 * 32 + lane];
        uint2 p2 = hw[u2 * 32 + lane];
        uint2 p3 = hw[u3 * 32 + lane];
        uint2 p4 = hw[u4 * 32 + lane];
        uint2 p5 = hw[u5 * 32 + lane];
        uint2 p6 = hw[u6 * 32 + lane];
        uint2 p7 = hw[u7 * 32 + lane];
        acc4(acc, h2f4(p0)); acc4(acc, h2f4(p1));
        acc4(acc, h2f4(p2)); acc4(acc, h2f4(p3));
        acc4(acc, h2f4(p4)); acc4(acc, h2f4(p5));
        acc4(acc, h2f4(p6)); acc4(acc, h2f4(p7));
    }
    for (; i + 2 <= e; i += 2) {
        int u0 = g_csr[i], u1 = g_csr[i + 1];
        uint2 p0 = hw[u0 * 32 + lane];
        uint2 p1 = hw[u1 * 32 + lane];
        acc4(acc, h2f4(p0)); acc4(acc, h2f4(p1));
    }
    if (i < e) acc4(acc, h2f4(hw[g_csr[i] * 32 + lane]));

    float dv = g_dinv[v];
    float4 b = ((const float4*)bias)[lane];
    float4 r;
    r.x = fmaf(dv, acc.x, b.x); r.y = fmaf(dv, acc.y, b.y);
    r.z = fmaf(dv, acc.z, b.z); r.w = fmaf(dv, acc.w, b.w);
    if (relu) {
        r.x = fmaxf(r.x, 0.f); r.y = fmaxf(r.y, 0.f);
        r.z = fmaxf(r.z, 0.f); r.w = fmaxf(r.w, 0.f);
    }
    out[v * 32 + lane] = make_uint2(hpack(r.x, r.y), hpack(r.z, r.w));
}

__global__ void agg_pool_kernel(const uint2* __restrict__ hw,
                                const float* __restrict__ bias,
                                const int* __restrict__ batch) {
    int gt = blockIdx.x * blockDim.x + threadIdx.x;
    int v = gt >> 5;
    int lane = gt & 31;
    if (v >= N_NODES) return;

    float4 acc = h2f4(hw[v * 32 + lane]);
    int s = g_rowptr[v], e = g_rowptr[v + 1];
    int i = s;
    for (; i + 8 <= e; i += 8) {
        int u0 = g_csr[i],     u1 = g_csr[i + 1];
        int u2 = g_csr[i + 2], u3 = g_csr[i + 3];
        int u4 = g_csr[i + 4], u5 = g_csr[i + 5];
        int u6 = g_csr[i + 6], u7 = g_csr[i + 7];
        uint2 p0 = hw[u0 * 32 + lane];
        uint2 p1 = hw[u1 * 32 + lane];
        uint2 p2 = hw[u2 * 32 + lane];
        uint2 p3 = hw[u3 * 32 + lane];
        uint2 p4 = hw[u4 * 32 + lane];
        uint2 p5 = hw[u5 * 32 + lane];
        uint2 p6 = hw[u6 * 32 + lane];
        uint2 p7 = hw[u7 * 32 + lane];
        acc4(acc, h2f4(p0)); acc4(acc, h2f4(p1));
        acc4(acc, h2f4(p2)); acc4(acc, h2f4(p3));
        acc4(acc, h2f4(p4)); acc4(acc, h2f4(p5));
        acc4(acc, h2f4(p6)); acc4(acc, h2f4(p7));
    }
    for (; i + 2 <= e; i += 2) {
        int u0 = g_csr[i], u1 = g_csr[i + 1];
        uint2 p0 = hw[u0 * 32 + lane];
        uint2 p1 = hw[u1 * 32 + lane];
        acc4(acc, h2f4(p0)); acc4(acc, h2f4(p1));
    }
    if (i < e) acc4(acc, h2f4(hw[g_csr[i] * 32 + lane]));

    float dv = g_dinv[v];
    float4 b = ((const float4*)bias)[lane];
    float4 r;
    r.x = fmaf(dv, acc.x, b.x); r.y = fmaf(dv, acc.y, b.y);
    r.z = fmaf(dv, acc.z, b.z); r.w = fmaf(dv, acc.w, b.w);

    int g = batch[v];
    float* base = &g_gs[g * D + lane * 4];
    atomicAdd(base + 0, r.x);
    atomicAdd(base + 1, r.y);
    atomicAdd(base + 2, r.z);
    atomicAdd(base + 3, r.w);
}

__global__ void final_kernel(const float* __restrict__ Wlin,
                             const float* __restrict__ blin,
                             float* __restrict__ out) {
    __shared__ float Ws[D * 3];
    int t = threadIdx.x;
    for (int i = t; i < D * 3; i += 128) Ws[i] = Wlin[i];
    __syncthreads();
    int g = t;
    float inv = 1.0f / fmaxf(g_gcnt[g], 1.0f);
    float o0 = blin[0], o1 = blin[1], o2 = blin[2];
    #pragma unroll 4
    for (int c = 0; c < D; ++c) {
        float p = g_gs[g * D + c] * inv;
        o0 = fmaf(p, Ws[c * 3 + 0], o0);
        o1 = fmaf(p, Ws[c * 3 + 1], o1);
        o2 = fmaf(p, Ws[c * 3 + 2], o2);
    }
    out[g * 3 + 0] = o0;
    out[g * 3 + 1] = o1;
    out[g * 3 + 2] = o2;
}

// ---------------- launch ----------------------------------------------------
extern "C" void kernel_launch(void* const* d_in, const int* in_sizes, int n_in,
                              void* d_out, int out_size) {
    const float* x     = (const float*)d_in[0];
    const int*   ei    = (const int*)d_in[1];
    const int*   batch = (const int*)d_in[2];
    const float* W1 = (const float*)d_in[3];
    const float* b1 = (const float*)d_in[4];
    const float* W2 = (const float*)d_in[5];
    const float* b2 = (const float*)d_in[6];
    const float* W3 = (const float*)d_in[7];
    const float* b3 = (const float*)d_in[8];
    const float* Wlin = (const float*)d_in[9];
    const float* blin = (const float*)d_in[10];
    float* out = (float*)d_out;

    const int* row = ei;
    const int* col = ei + N_EDGES;

    cudaFuncSetAttribute(mma_gemm_kernel,
                         cudaFuncAttributeMaxDynamicSharedMemorySize, SM_TOT);

    __half *xb_p = nullptr, *hw_p = nullptr, *hb_p = nullptr, *wt_p = nullptr;
    cudaGetSymbolAddress((void**)&xb_p, g_xb);
    cudaGetSymbolAddress((void**)&hw_p, g_hw);
    cudaGetSymbolAddress((void**)&hb_p, g_hb);
    cudaGetSymbolAddress((void**)&wt_p, g_wt);

    static cudaStream_t s_side = nullptr;
    static cudaEvent_t  ev_fork = nullptr, ev_dinv = nullptr, ev_csr = nullptr;
    static cudaEvent_t  ev1a = nullptr, ev1b = nullptr, ev2a = nullptr, ev2b = nullptr;
    if (s_side == nullptr) {
        cudaStreamCreateWithFlags(&s_side, cudaStreamNonBlocking);
        cudaEventCreateWithFlags(&ev_fork, cudaEventDisableTiming);
        cudaEventCreateWithFlags(&ev_dinv, cudaEventDisableTiming);
        cudaEventCreateWithFlags(&ev_csr,  cudaEventDisableTiming);
        cudaEventCreateWithFlags(&ev1a, cudaEventDisableTiming);
        cudaEventCreateWithFlags(&ev1b, cudaEventDisableTiming);
        cudaEventCreateWithFlags(&ev2a, cudaEventDisableTiming);
        cudaEventCreateWithFlags(&ev2b, cudaEventDisableTiming);
    }

    const int edgeBlocks = (N_EDGES + 255) / 256;
    const int zeroBlocks = (N_NODES + 255) / 256;
    const int convBlocks = (N_NODES * 32 + 255) / 256;
    const int gemmGridF  = (N_NODES + 127) / 128;              // 391
    const int gemmGridA  = NA / 128;                           // 196
    const int gemmGridB  = (N_NODES - NA + 127) / 128;         // 195
    const int aggBlocksF = (N_NODES * 32 + 255) / 256;
    const int aggBlocksA = (NA * 32 + 255) / 256;
    const int aggBlocksB = ((N_NODES - NA) * 32 + 255) / 256;

    // fork side stream
    cudaEventRecord(ev_fork, 0);
    cudaStreamWaitEvent(s_side, ev_fork, 0);

    // ---- side stream: CSR build chain (R8-exact) ----
    zero_kernel<<<zeroBlocks, 256, 0, s_side>>>();
    hist_count_kernel<<<edgeBlocks, 256, 0, s_side>>>(col, batch);
    scan_part_kernel<<<SCAN_BLKS, 1024, 0, s_side>>>();
    cudaEventRecord(ev_dinv, s_side);
    scan_bsum_kernel<<<1, 32, 0, s_side>>>();
    scan_final_kernel<<<(N_NODES + 1023) / 1024, 1024, 0, s_side>>>();
    scatter_kernel<<<edgeBlocks, 256, 0, s_side>>>(row, col);
    cudaEventRecord(ev_csr, s_side);

    // ---- main stream ----
    conv_kernel<<<convBlocks, 256>>>(x, W1, W2, W3);
    cudaStreamWaitEvent(0, ev_dinv, 0);
    // layer 1: xb @ W1 -> hw (full)
    mma_gemm_kernel<<<gemmGridF, 256, SM_TOT>>>(xb_p, wt_p, hw_p, 0, N_NODES);
    cudaStreamWaitEvent(0, ev_csr, 0);

    // ---- boundary 1: agg1 reads hw -> hb ; gemm2 reads hb -> xb ----
    // (gemm2 output xb is disjoint from agg1's gather source hw: overlap safe)
    agg_kernel<<<aggBlocksA, 256>>>((const uint2*)hw_p, b1, (uint2*)hb_p, 1,
                                    0, NA);
    cudaEventRecord(ev1a, 0);
    cudaStreamWaitEvent(s_side, ev1a, 0);
    agg_kernel<<<aggBlocksB, 256, 0, s_side>>>((const uint2*)hw_p, b1,
                                               (uint2*)hb_p, 1, NA, N_NODES);
    cudaEventRecord(ev1b, s_side);
    mma_gemm_kernel<<<gemmGridA, 256, SM_TOT>>>(hb_p, wt_p + D * D, xb_p,
                                                0, N_NODES);
    cudaStreamWaitEvent(0, ev1b, 0);
    mma_gemm_kernel<<<gemmGridB, 256, SM_TOT>>>(hb_p, wt_p + D * D, xb_p,
                                                NA, N_NODES);

    // ---- boundary 2: agg2 reads xb -> hb ; gemm3 reads hb -> hw ----
    agg_kernel<<<aggBlocksA, 256>>>((const uint2*)xb_p, b2, (uint2*)hb_p, 1,
                                    0, NA);
    cudaEventRecord(ev2a, 0);
    cudaStreamWaitEvent(s_side, ev2a, 0);
    agg_kernel<<<aggBlocksB, 256, 0, s_side>>>((const uint2*)xb_p, b2,
                                               (uint2*)hb_p, 1, NA, N_NODES);
    cudaEventRecord(ev2b, s_side);
    mma_gemm_kernel<<<gemmGridA, 256, SM_TOT>>>(hb_p, wt_p + 2 * D * D, hw_p,
                                                0, N_NODES);
    cudaStreamWaitEvent(0, ev2b, 0);
    mma_gemm_kernel<<<gemmGridB, 256, SM_TOT>>>(hb_p, wt_p + 2 * D * D, hw_p,
                                                NA, N_NODES);

    // pool + head
    agg_pool_kernel<<<aggBlocksF, 256>>>((const uint2*)hw_p, b3, batch);
    final_kernel<<<1, 128>>>(Wlin, blin, out);
}

// round 14
// speedup vs baseline: 1.0904x; 1.0904x over previous
#include <cuda_runtime.h>
#include <cuda_fp16.h>
#include <cstdint>

#define N_NODES  50000
#define N_EDGES  800000
#define N_GRAPHS 128
#define D        128
#define ELL_CAP  96

// ---------------- scratch (device globals; no allocation allowed) ----------
__device__ __half g_xb[N_NODES * D];   // x converted to fp16
__device__ __half g_hw[N_NODES * D];   // GEMM output (scaled by dinv)
__device__ __half g_hb[N_NODES * D];   // activations
__device__ __half g_wt[3 * D * D];     // transposed weights [N][K] fp16
__device__ int    g_cnt[N_NODES];      // in-degree (built by ell_build)
__device__ float  g_dinv[N_NODES];
__device__ int    g_ell[N_NODES * ELL_CAP];  // padded neighbor lists
__device__ float  g_gs[N_GRAPHS * D];
__device__ float  g_gcnt[N_GRAPHS];

// ---------------- small helpers --------------------------------------------
__device__ __forceinline__ unsigned hpack(float lo, float hi) {
    unsigned r;
    asm("cvt.rn.f16x2.f32 %0, %1, %2;" : "=r"(r) : "f"(hi), "f"(lo));
    return r;
}
__device__ __forceinline__ float4 h2f4(uint2 p) {
    __half2 a = *reinterpret_cast<__half2*>(&p.x);
    __half2 b = *reinterpret_cast<__half2*>(&p.y);
    float2 fa = __half22float2(a);
    float2 fb = __half22float2(b);
    return make_float4(fa.x, fa.y, fb.x, fb.y);
}
__device__ __forceinline__ void acc4(float4& a, float4 t) {
    a.x += t.x; a.y += t.y; a.z += t.z; a.w += t.w;
}
__device__ __forceinline__ uint32_t smem_u32(const void* p) {
    uint32_t a;
    asm("{ .reg .u64 t; cvta.to.shared.u64 t, %1; cvt.u32.u64 %0, t; }"
        : "=r"(a) : "l"(p));
    return a;
}

// ---------------- mma helpers ------------------------------------------------
__device__ __forceinline__ void ldsm_x4(uint32_t& r0, uint32_t& r1,
                                        uint32_t& r2, uint32_t& r3,
                                        uint32_t addr) {
    asm volatile("ldmatrix.sync.aligned.m8n8.x4.shared.b16 {%0,%1,%2,%3}, [%4];"
                 : "=r"(r0), "=r"(r1), "=r"(r2), "=r"(r3) : "r"(addr));
}
__device__ __forceinline__ void ldsm_x2(uint32_t& r0, uint32_t& r1,
                                        uint32_t addr) {
    asm volatile("ldmatrix.sync.aligned.m8n8.x2.shared.b16 {%0,%1}, [%2];"
                 : "=r"(r0), "=r"(r1) : "r"(addr));
}
__device__ __forceinline__ void mma16816(float& d0, float& d1, float& d2, float& d3,
                                         uint32_t a0, uint32_t a1, uint32_t a2,
                                         uint32_t a3, uint32_t b0, uint32_t b1) {
    asm volatile(
        "mma.sync.aligned.m16n8k16.row.col.f32.f16.f16.f32 "
        "{%0,%1,%2,%3}, {%4,%5,%6,%7}, {%8,%9}, {%0,%1,%2,%3};"
        : "+f"(d0), "+f"(d1), "+f"(d2), "+f"(d3)
        : "r"(a0), "r"(a1), "r"(a2), "r"(a3), "r"(b0), "r"(b1));
}

// ---------------- setup kernels --------------------------------------------
__global__ void zero_kernel() {
    int i = blockIdx.x * blockDim.x + threadIdx.x;
    if (i < N_NODES) g_cnt[i] = 0;
    if (i < N_GRAPHS * D) g_gs[i] = 0.f;
    if (i < N_GRAPHS) g_gcnt[i] = 0.f;
}

// ONE-pass graph build: ELL insert + per-graph node counts
__global__ void ell_build_kernel(const int* __restrict__ row,
                                 const int* __restrict__ col,
                                 const int* __restrict__ batch) {
    int i = blockIdx.x * blockDim.x + threadIdx.x;
    if (i < N_EDGES) {
        int c = col[i];
        int p = atomicAdd(&g_cnt[c], 1);
        if (p < ELL_CAP) g_ell[c * ELL_CAP + p] = row[i];
    }
    if (i < N_NODES) atomicAdd(&g_gcnt[batch[i]], 1.0f);
}

__global__ void dinv_kernel() {
    int i = blockIdx.x * blockDim.x + threadIdx.x;
    if (i < N_NODES) g_dinv[i] = rsqrtf((float)(g_cnt[i] + 1));
}

// convert x -> fp16 AND transpose+convert all 3 weight matrices (main stream)
__global__ void conv_kernel(const float* __restrict__ x,
                            const float* __restrict__ W1,
                            const float* __restrict__ W2,
                            const float* __restrict__ W3) {
    int i = blockIdx.x * blockDim.x + threadIdx.x;
    if (i < N_NODES * (D / 4)) {
        float4 v = ((const float4*)x)[i];
        uint2 o;
        o.x = hpack(v.x, v.y);
        o.y = hpack(v.z, v.w);
        ((uint2*)g_xb)[i] = o;
    }
    if (i < 3 * D * D) {
        int l = i >> 14;
        int r = i & (D * D - 1);
        int k = r >> 7, n = r & 127;
        const float* W = (l == 0) ? W1 : ((l == 1) ? W2 : W3);
        g_wt[l * D * D + n * D + k] = __float2half(W[k * D + n]);
    }
}

// ---------------- shared GEMM pieces ----------------------------------------
#define SM_STRIDE 136
#define SM_ROWB   (SM_STRIDE * 2)
#define SM_A_OFF  0
#define SM_B_OFF  (128 * SM_ROWB)
#define SM_TOT    (2 * 128 * SM_ROWB)

__device__ __forceinline__ void stage_B(char* smem, const __half* Wt, int tid) {
    const uint4* Bin = (const uint4*)Wt;
    #pragma unroll 4
    for (int i = tid; i < 2048; i += 256) {
        int r = i >> 4, g = i & 15;
        *(uint4*)(smem + SM_B_OFF + r * SM_ROWB + g * 16) = Bin[i];
    }
}

__device__ __forceinline__ void mma_body(char* smem, uint32_t sb,
                                         __half* __restrict__ out,
                                         int row0, int n, int wid, int lane) {
    int m_base = wid * 16;
    uint32_t a_addr = sb + SM_A_OFF
                    + (uint32_t)(m_base + (lane & 15)) * SM_ROWB
                    + (uint32_t)(lane >> 4) * 16;
    uint32_t b_addr = sb + SM_B_OFF
                    + (uint32_t)(lane & 7) * SM_ROWB
                    + (uint32_t)((lane >> 3) & 1) * 16;

    float acc[16][4];
    #pragma unroll
    for (int j = 0; j < 16; j++)
        #pragma unroll
        for (int q = 0; q < 4; q++) acc[j][q] = 0.f;

    #pragma unroll
    for (int kk = 0; kk < 8; kk++) {
        uint32_t a0, a1, a2, a3;
        ldsm_x4(a0, a1, a2, a3, a_addr + kk * 32);
        #pragma unroll
        for (int j = 0; j < 16; j++) {
            uint32_t b0, b1;
            ldsm_x2(b0, b1, b_addr + (uint32_t)j * 8 * SM_ROWB + kk * 32);
            mma16816(acc[j][0], acc[j][1], acc[j][2], acc[j][3],
                     a0, a1, a2, a3, b0, b1);
        }
    }

    int quad = lane >> 2;
    int tcol = (lane & 3) * 2;
    int r0 = row0 + m_base + quad;
    int r1 = r0 + 8;
    float dv0 = (r0 < n) ? g_dinv[r0] : 0.f;
    float dv1 = (r1 < n) ? g_dinv[r1] : 0.f;
    unsigned* o0 = (unsigned*)(out + (size_t)(r0 < n ? r0 : 0) * D);
    unsigned* o1 = (unsigned*)(out + (size_t)(r1 < n ? r1 : 0) * D);
    #pragma unroll
    for (int j = 0; j < 16; j++) {
        int nc = j * 8 + tcol;
        if (r0 < n) o0[nc >> 1] = hpack(acc[j][0] * dv0, acc[j][1] * dv0);
        if (r1 < n) o1[nc >> 1] = hpack(acc[j][2] * dv1, acc[j][3] * dv1);
    }
}

__global__ void __launch_bounds__(256, 2)
mma_gemm_kernel(const __half* __restrict__ in,
                const __half* __restrict__ Wt,
                __half* __restrict__ out, int n) {
    extern __shared__ char smem[];
    uint32_t sb = smem_u32(smem);
    int tid = threadIdx.x, wid = tid >> 5, lane = tid & 31;
    int row0 = blockIdx.x * 128;

    const uint4* Ain = (const uint4*)(in + (size_t)row0 * D);
    #pragma unroll 4
    for (int i = tid; i < 2048; i += 256) {
        int r = i >> 4, g = i & 15;
        uint4 va = make_uint4(0u, 0u, 0u, 0u);
        if (row0 + r < n) va = Ain[i];
        *(uint4*)(smem + SM_A_OFF + r * SM_ROWB + g * 16) = va;
    }
    stage_B(smem, Wt, tid);
    __syncthreads();
    mma_body(smem, sb, out, row0, n, wid, lane);
}

// ---------------- aggregation: warp per node, ELL gather, fp32 acc ---------
__global__ void agg_kernel(const uint2* __restrict__ hw,
                           const float* __restrict__ bias,
                           uint2* __restrict__ out, int relu) {
    int gt = blockIdx.x * blockDim.x + threadIdx.x;
    int v = gt >> 5;
    int lane = gt & 31;
    if (v >= N_NODES) return;

    float4 acc = h2f4(hw[v * 32 + lane]);      // self loop
    const int* nb = g_ell + v * ELL_CAP;
    int e = g_cnt[v];
    int i = 0;
    for (; i + 8 <= e; i += 8) {
        int u0 = nb[i],     u1 = nb[i + 1];
        int u2 = nb[i + 2], u3 = nb[i + 3];
        int u4 = nb[i + 4], u5 = nb[i + 5];
        int u6 = nb[i + 6], u7 = nb[i + 7];
        uint2 p0 = hw[u0 * 32 + lane];
        uint2 p1 = hw[u1 * 32 + lane];
        uint2 p2 = hw[u2 * 32 + lane];
        uint2 p3 = hw[u3 * 32 + lane];
        uint2 p4 = hw[u4 * 32 + lane];
        uint2 p5 = hw[u5 * 32 + lane];
        uint2 p6 = hw[u6 * 32 + lane];
        uint2 p7 = hw[u7 * 32 + lane];
        acc4(acc, h2f4(p0)); acc4(acc, h2f4(p1));
        acc4(acc, h2f4(p2)); acc4(acc, h2f4(p3));
        acc4(acc, h2f4(p4)); acc4(acc, h2f4(p5));
        acc4(acc, h2f4(p6)); acc4(acc, h2f4(p7));
    }
    for (; i + 2 <= e; i += 2) {
        int u0 = nb[i], u1 = nb[i + 1];
        uint2 p0 = hw[u0 * 32 + lane];
        uint2 p1 = hw[u1 * 32 + lane];
        acc4(acc, h2f4(p0)); acc4(acc, h2f4(p1));
    }
    if (i < e) acc4(acc, h2f4(hw[nb[i] * 32 + lane]));

    float dv = g_dinv[v];
    float4 b = ((const float4*)bias)[lane];
    float4 r;
    r.x = fmaf(dv, acc.x, b.x); r.y = fmaf(dv, acc.y, b.y);
    r.z = fmaf(dv, acc.z, b.z); r.w = fmaf(dv, acc.w, b.w);
    if (relu) {
        r.x = fmaxf(r.x, 0.f); r.y = fmaxf(r.y, 0.f);
        r.z = fmaxf(r.z, 0.f); r.w = fmaxf(r.w, 0.f);
    }
    out[v * 32 + lane] = make_uint2(hpack(r.x, r.y), hpack(r.z, r.w));
}

__global__ void agg_pool_kernel(const uint2* __restrict__ hw,
                                const float* __restrict__ bias,
                                const int* __restrict__ batch) {
    int gt = blockIdx.x * blockDim.x + threadIdx.x;
    int v = gt >> 5;
    int lane = gt & 31;
    if (v >= N_NODES) return;

    float4 acc = h2f4(hw[v * 32 + lane]);
    const int* nb = g_ell + v * ELL_CAP;
    int e = g_cnt[v];
    int i = 0;
    for (; i + 8 <= e; i += 8) {
        int u0 = nb[i],     u1 = nb[i + 1];
        int u2 = nb[i + 2], u3 = nb[i + 3];
        int u4 = nb[i + 4], u5 = nb[i + 5];
        int u6 = nb[i + 6], u7 = nb[i + 7];
        uint2 p0 = hw[u0 * 32 + lane];
        uint2 p1 = hw[u1 * 32 + lane];
        uint2 p2 = hw[u2 * 32 + lane];
        uint2 p3 = hw[u3 * 32 + lane];
        uint2 p4 = hw[u4 * 32 + lane];
        uint2 p5 = hw[u5 * 32 + lane];
        uint2 p6 = hw[u6 * 32 + lane];
        uint2 p7 = hw[u7 * 32 + lane];
        acc4(acc, h2f4(p0)); acc4(acc, h2f4(p1));
        acc4(acc, h2f4(p2)); acc4(acc, h2f4(p3));
        acc4(acc, h2f4(p4)); acc4(acc, h2f4(p5));
        acc4(acc, h2f4(p6)); acc4(acc, h2f4(p7));
    }
    for (; i + 2 <= e; i += 2) {
        int u0 = nb[i], u1 = nb[i + 1];
        uint2 p0 = hw[u0 * 32 + lane];
        uint2 p1 = hw[u1 * 32 + lane];
        acc4(acc, h2f4(p0)); acc4(acc, h2f4(p1));
    }
    if (i < e) acc4(acc, h2f4(hw[nb[i] * 32 + lane]));

    float dv = g_dinv[v];
    float4 b = ((const float4*)bias)[lane];
    float4 r;
    r.x = fmaf(dv, acc.x, b.x); r.y = fmaf(dv, acc.y, b.y);
    r.z = fmaf(dv, acc.z, b.z); r.w = fmaf(dv, acc.w, b.w);

    int g = batch[v];
    float* base = &g_gs[g * D + lane * 4];
    atomicAdd(base + 0, r.x);
    atomicAdd(base + 1, r.y);
    atomicAdd(base + 2, r.z);
    atomicAdd(base + 3, r.w);
}

__global__ void final_kernel(const float* __restrict__ Wlin,
                             const float* __restrict__ blin,
                             float* __restrict__ out) {
    __shared__ float Ws[D * 3];
    int t = threadIdx.x;
    for (int i = t; i < D * 3; i += 128) Ws[i] = Wlin[i];
    __syncthreads();
    int g = t;
    float inv = 1.0f / fmaxf(g_gcnt[g], 1.0f);
    float o0 = blin[0], o1 = blin[1], o2 = blin[2];
    #pragma unroll 4
    for (int c = 0; c < D; ++c) {
        float p = g_gs[g * D + c] * inv;
        o0 = fmaf(p, Ws[c * 3 + 0], o0);
        o1 = fmaf(p, Ws[c * 3 + 1], o1);
        o2 = fmaf(p, Ws[c * 3 + 2], o2);
    }
    out[g * 3 + 0] = o0;
    out[g * 3 + 1] = o1;
    out[g * 3 + 2] = o2;
}

// ---------------- launch ----------------------------------------------------
extern "C" void kernel_launch(void* const* d_in, const int* in_sizes, int n_in,
                              void* d_out, int out_size) {
    const float* x     = (const float*)d_in[0];
    const int*   ei    = (const int*)d_in[1];
    const int*   batch = (const int*)d_in[2];
    const float* W1 = (const float*)d_in[3];
    const float* b1 = (const float*)d_in[4];
    const float* W2 = (const float*)d_in[5];
    const float* b2 = (const float*)d_in[6];
    const float* W3 = (const float*)d_in[7];
    const float* b3 = (const float*)d_in[8];
    const float* Wlin = (const float*)d_in[9];
    const float* blin = (const float*)d_in[10];
    float* out = (float*)d_out;

    const int* row = ei;
    const int* col = ei + N_EDGES;

    cudaFuncSetAttribute(mma_gemm_kernel,
                         cudaFuncAttributeMaxDynamicSharedMemorySize, SM_TOT);

    __half *xb_p = nullptr, *hw_p = nullptr, *hb_p = nullptr, *wt_p = nullptr;
    cudaGetSymbolAddress((void**)&xb_p, g_xb);
    cudaGetSymbolAddress((void**)&hw_p, g_hw);
    cudaGetSymbolAddress((void**)&hb_p, g_hb);
    cudaGetSymbolAddress((void**)&wt_p, g_wt);

    static cudaStream_t s_side = nullptr;
    static cudaEvent_t  ev_fork = nullptr, ev_ready = nullptr;
    if (s_side == nullptr) {
        cudaStreamCreateWithFlags(&s_side, cudaStreamNonBlocking);
        cudaEventCreateWithFlags(&ev_fork,  cudaEventDisableTiming);
        cudaEventCreateWithFlags(&ev_ready, cudaEventDisableTiming);
    }

    const int edgeBlocks = (N_EDGES + 255) / 256;
    const int zeroBlocks = (N_NODES + 255) / 256;
    const int convBlocks = (N_NODES * 32 + 255) / 256;
    const int gemmGrid   = (N_NODES + 127) / 128;
    const int aggBlocks  = (N_NODES * 32 + 255) / 256;

    // fork side stream off the main (captured) stream
    cudaEventRecord(ev_fork, 0);
    cudaStreamWaitEvent(s_side, ev_fork, 0);

    // ---- side stream: one-pass ELL build ----
    zero_kernel<<<zeroBlocks, 256, 0, s_side>>>();
    ell_build_kernel<<<edgeBlocks, 256, 0, s_side>>>(row, col, batch);
    dinv_kernel<<<zeroBlocks, 256, 0, s_side>>>();
    cudaEventRecord(ev_ready, s_side);   // ell + cnt + dinv + gcnt ready

    // ---- main stream ----
    conv_kernel<<<convBlocks, 256>>>(x, W1, W2, W3);
    cudaStreamWaitEvent(0, ev_ready, 0);
    // layer 1
    mma_gemm_kernel<<<gemmGrid, 256, SM_TOT>>>(xb_p, wt_p, hw_p, N_NODES);
    agg_kernel<<<aggBlocks, 256>>>((const uint2*)hw_p, b1, (uint2*)hb_p, 1);
    // layer 2
    mma_gemm_kernel<<<gemmGrid, 256, SM_TOT>>>(hb_p, wt_p + D * D, hw_p, N_NODES);
    agg_kernel<<<aggBlocks, 256>>>((const uint2*)hw_p, b2, (uint2*)hb_p, 1);
    // layer 3
    mma_gemm_kernel<<<gemmGrid, 256, SM_TOT>>>(hb_p, wt_p + 2 * D * D, hw_p, N_NODES);
    agg_pool_kernel<<<aggBlocks, 256>>>((const uint2*)hw_p, b3, batch);

    final_kernel<<<1, 128>>>(Wlin, blin, out);
}